// round 14
// baseline (speedup 1.0000x reference)
#include <cuda_runtime.h>
#include <cuda_fp16.h>
#include <math.h>
#include <stdint.h>

#define BTOK 4096
#define DIN  512
#define HDIM 1024
#define NEXP 16
#define KSEL 4
#define NCLS 20
#define EPSN 1e-5f

// ---- device scratch (no allocation allowed) ----
__device__ __half g_combh[BTOK * DIN];          // hi plane (GEMM1 A, gate A hi)
__device__ __half g_combl[BTOK * DIN];          // lo plane (gate A lo)
__device__ float  g_g1[BTOK * HDIM];
__device__ int    g_tidx[BTOK * KSEL];
__device__ float  g_tw[BTOK * KSEL];
__device__ int    g_counts[NEXP];
__device__ int    g_cursor[NEXP];
__device__ int    g_offsets[NEXP + 1];
__device__ int    g_rowinfo[BTOK * KSEL];
__device__ __half g_h1f[BTOK * KSEL * HDIM];
__device__ __half g_h2f[BTOK * KSEL * HDIM];
__device__ __half g_fusedf[BTOK * HDIM];
__device__ float  g_o1[BTOK * 512];
__device__ __half g_ew1f[NEXP * DIN * HDIM];
__device__ __half g_ew2f[NEXP * HDIM * HDIM];
__device__ __half g_fw1f[HDIM * 512];
__device__ __half g_gw1h[DIN * HDIM];
__device__ __half g_gw1l[DIN * HDIM];

__device__ __forceinline__ float gelu_f(float x) {
    return 0.5f * x * (1.0f + erff(x * 0.70710678118654752440f));
}
__device__ __forceinline__ uint32_t smem_u32(const void* p) {
    uint32_t a;
    asm("{ .reg .u64 t; cvta.to.shared.u64 t, %1; cvt.u32.u64 %0, t; }" : "=r"(a) : "l"(p));
    return a;
}
__device__ __forceinline__ uint4 ldm4(uint32_t addr) {
    uint4 r;
    asm volatile("ldmatrix.sync.aligned.m8n8.x4.shared.b16 {%0,%1,%2,%3}, [%4];"
                 : "=r"(r.x), "=r"(r.y), "=r"(r.z), "=r"(r.w) : "r"(addr));
    return r;
}
__device__ __forceinline__ void mma_fp16(float* c, const uint4& a, uint32_t b0, uint32_t b1) {
    asm volatile(
        "mma.sync.aligned.m16n8k16.row.col.f32.f16.f16.f32 "
        "{%0,%1,%2,%3}, {%4,%5,%6,%7}, {%8,%9}, {%0,%1,%2,%3};"
        : "+f"(c[0]), "+f"(c[1]), "+f"(c[2]), "+f"(c[3])
        : "r"(a.x), "r"(a.y), "r"(a.z), "r"(a.w), "r"(b0), "r"(b1));
}
__device__ __forceinline__ uint32_t pkh(__half a, __half b) {
    return (uint32_t)__half_as_ushort(a) | ((uint32_t)__half_as_ushort(b) << 16);
}
__device__ __forceinline__ void split2h(float x, __half& h, __half& l) {
    h = __float2half_rn(x);
    l = __float2half_rn(x - __half2float(h));
}

// ---- concat -> fp16 hi/lo planes only ----
__global__ void concat_kernel(const float* __restrict__ wifi, const float* __restrict__ rfid,
                              __half* __restrict__ ch, __half* __restrict__ cl) {
    int i = blockIdx.x * 256 + threadIdx.x;
    if (i < BTOK * DIN) {
        int b = i >> 9, c = i & 511;
        float v = (c < 256) ? wifi[b * 256 + c] : rfid[b * 256 + (c - 256)];
        __half h, l; split2h(v, h, l);
        ch[i] = h; cl[i] = l;
    }
}

// ---- weight transpose + fp16 convert (1 plane): W[e,K,N] -> T[e,N,K] ----
__global__ void wsplit_kernel(const float* __restrict__ W, __half* __restrict__ Tf,
                              int K, int N) {
    __shared__ float tile[32][33];
    size_t base = (size_t)blockIdx.z * K * N;
    int k0 = blockIdx.y * 32, n0 = blockIdx.x * 32;
    int tx = threadIdx.x, ty = threadIdx.y;
#pragma unroll
    for (int i = 0; i < 32; i += 8)
        tile[ty + i][tx] = W[base + (size_t)(k0 + ty + i) * N + n0 + tx];
    __syncthreads();
#pragma unroll
    for (int i = 0; i < 32; i += 8) {
        int n = n0 + ty + i, k = k0 + tx;
        Tf[base + (size_t)n * K + k] = __float2half_rn(tile[tx][ty + i]);
    }
}

// ---- weight transpose + fp16 hi/lo split (2 planes) ----
__global__ void wsplit2_kernel(const float* __restrict__ W,
                               __half* __restrict__ Th, __half* __restrict__ Tl,
                               int K, int N) {
    __shared__ float tile[32][33];
    int k0 = blockIdx.y * 32, n0 = blockIdx.x * 32;
    int tx = threadIdx.x, ty = threadIdx.y;
#pragma unroll
    for (int i = 0; i < 32; i += 8)
        tile[ty + i][tx] = W[(size_t)(k0 + ty + i) * N + n0 + tx];
    __syncthreads();
#pragma unroll
    for (int i = 0; i < 32; i += 8) {
        int n = n0 + ty + i, k = k0 + tx;
        __half h, l; split2h(tile[tx][ty + i], h, l);
        Th[(size_t)n * K + k] = h;
        Tl[(size_t)n * K + k] = l;
    }
}

// ---------------------------------------------------------------------------
// fp16 1-pass HMMA GEMM (R11 mainloop: k-chunk 32, register prefetch, occ 2).
// A fp16 [M,K]; B fp16 [N,K]. SMEM/buffer: A@0, B@10240 -> 20480.
// ---------------------------------------------------------------------------
static constexpr int WG_SMEM = 2 * 20480;

template<bool SEG, bool GATHER, bool SCATTER, bool BN, bool OUTS>
__global__ void __launch_bounds__(256, 2) w_gemm(
    const __half* __restrict__ Ap, const __half* __restrict__ Bp,
    float* __restrict__ C, __half* __restrict__ Cf,
    int Mfixed, int N, int K,
    const int* __restrict__ offsets, const int* __restrict__ rowinfo,
    const float* __restrict__ bias,
    const float* __restrict__ bng, const float* __restrict__ bnb,
    const float* __restrict__ bnm, const float* __restrict__ bnv)
{
    extern __shared__ __align__(16) char sm[];
    int m0 = 0, M = Mfixed;
    if (SEG) {
        int e = blockIdx.z;
        m0 = offsets[e];
        M  = offsets[e + 1] - m0;
        Bp += (size_t)e * K * N;
        bias += (size_t)e * N;
        if (BN) { bng += (size_t)e * N; bnb += (size_t)e * N;
                  bnm += (size_t)e * N; bnv += (size_t)e * N; }
    }
    const int mtile = blockIdx.x * 128;
    if (mtile >= M) return;
    const int ntile = blockIdx.y * 128;

    const int tid = threadIdx.x, lane = tid & 31, wid = tid >> 5;
    const int warpM = wid & 3, warpN = wid >> 2;
    const uint32_t smBase = smem_u32(sm);

    const int acg = tid & 7;
    const __half* aP[4]; bool aval[4]; uint32_t aDst[4];
#pragma unroll
    for (int i = 0; i < 4; i++) {
        int row = (tid >> 3) + i * 32;
        bool v = (mtile + row) < M;
        aval[i] = v;
        int tok = 0;
        if (v) { int gr = m0 + mtile + row; tok = GATHER ? (rowinfo[gr] >> 2) : gr; }
        aP[i] = Ap + (size_t)tok * K + acg * 4;
        aDst[i] = (uint32_t)(row * 80 + acg * 8);
    }
    const __half* bPtr[2]; uint32_t bDst[2];
#pragma unroll
    for (int i = 0; i < 2; i++) {
        int idx = tid + (i << 8);
        int row = idx >> 2, cg = idx & 3;
        bPtr[i] = Bp + (size_t)(ntile + row) * K + cg * 8;
        bDst[i] = 10240u + (uint32_t)(row * 80 + cg * 16);
    }

    const int qa = lane >> 3, ra = lane & 7;
    const int lrow = ((qa & 1) << 3) + ra;
    const int lcolB = ((qa >> 1) << 3) * 2;
    const uint32_t aFragOff = (uint32_t)((warpM * 32 + lrow) * 80) + lcolB;
    const uint32_t bFragOff = (uint32_t)((warpN * 64 + lrow) * 80) + lcolB + 10240u;

    float acc[2][8][4];
#pragma unroll
    for (int mt = 0; mt < 2; mt++)
#pragma unroll
        for (int nt = 0; nt < 8; nt++)
#pragma unroll
            for (int q = 0; q < 4; q++) acc[mt][nt][q] = 0.0f;

    const int NC = K >> 5;
    const uint2 z2 = make_uint2(0u, 0u);

    {
        char* base = sm;
#pragma unroll
        for (int i = 0; i < 4; i++)
            *(uint2*)(base + aDst[i]) = aval[i] ? *(const uint2*)aP[i] : z2;
#pragma unroll
        for (int i = 0; i < 2; i++)
            *(uint4*)(base + bDst[i]) = *(const uint4*)bPtr[i];
    }
    __syncthreads();

    for (int c = 0; c < NC; c++) {
        uint2 aR[4]; uint4 bR[2];
        const bool pf = (c + 1) < NC;
        if (pf) {
            const int kc = (c + 1) << 5;
#pragma unroll
            for (int i = 0; i < 4; i++)
                aR[i] = aval[i] ? *(const uint2*)(aP[i] + kc) : z2;
#pragma unroll
            for (int i = 0; i < 2; i++)
                bR[i] = *(const uint4*)(bPtr[i] + kc);
        }
        const uint32_t bb = smBase + (uint32_t)(c & 1) * 20480u;
#pragma unroll
        for (int ks = 0; ks < 2; ks++) {
            const uint32_t kso = ks * 32;
            uint4 ah[2];
#pragma unroll
            for (int mt = 0; mt < 2; mt++)
                ah[mt] = ldm4(bb + aFragOff + mt * 1280u + kso);
            uint32_t bf[8][2];
#pragma unroll
            for (int np = 0; np < 4; np++) {
                uint4 h = ldm4(bb + bFragOff + np * 1280u + kso);
                bf[2*np][0] = h.x; bf[2*np][1] = h.z;
                bf[2*np+1][0] = h.y; bf[2*np+1][1] = h.w;
            }
#pragma unroll
            for (int mt = 0; mt < 2; mt++)
#pragma unroll
                for (int nt = 0; nt < 8; nt++)
                    mma_fp16(acc[mt][nt], ah[mt], bf[nt][0], bf[nt][1]);
        }
        if (pf) {
            char* base = sm + ((c + 1) & 1) * 20480;
#pragma unroll
            for (int i = 0; i < 4; i++)
                *(uint2*)(base + aDst[i]) = aR[i];
#pragma unroll
            for (int i = 0; i < 2; i++)
                *(uint4*)(base + bDst[i]) = bR[i];
        }
        __syncthreads();
    }

    const int g = lane >> 2, tt = lane & 3;
#pragma unroll
    for (int mt = 0; mt < 2; mt++) {
#pragma unroll
        for (int half = 0; half < 2; half++) {
            int rl = mtile + warpM * 32 + mt * 16 + half * 8 + g;
            if (rl < M) {
                int gr = m0 + rl;
                int crow = SCATTER ? rowinfo[gr] : gr;
                size_t rowoff = (size_t)crow * N;
#pragma unroll
                for (int nt = 0; nt < 8; nt++) {
                    int cn = ntile + warpN * 64 + nt * 8 + tt * 2;
                    float x0 = acc[mt][nt][half * 2 + 0] + __ldg(bias + cn);
                    float x1 = acc[mt][nt][half * 2 + 1] + __ldg(bias + cn + 1);
                    if (BN) {
                        x0 = gelu_f((x0 - __ldg(bnm + cn)) * rsqrtf(__ldg(bnv + cn) + EPSN)
                                    * __ldg(bng + cn) + __ldg(bnb + cn));
                        x1 = gelu_f((x1 - __ldg(bnm + cn + 1)) * rsqrtf(__ldg(bnv + cn + 1) + EPSN)
                                    * __ldg(bng + cn + 1) + __ldg(bnb + cn + 1));
                    }
                    if (OUTS) {
                        *(uint32_t*)(Cf + rowoff + cn) =
                            pkh(__float2half_rn(x0), __float2half_rn(x1));
                    } else {
                        *(float2*)(C + rowoff + cn) = make_float2(x0, x1);
                    }
                }
            }
        }
    }
}

// ---------------------------------------------------------------------------
// Gate GEMM: fp16 3-pass (AhBh + AlBh + AhBl), near-fp32. (R11 version)
// ---------------------------------------------------------------------------
static constexpr int GG_SMEM = 2 * 40960;

__global__ void __launch_bounds__(256, 1) gate_hmma(
    const __half* __restrict__ Ahp, const __half* __restrict__ Alp,
    const __half* __restrict__ Bhp, const __half* __restrict__ Blp,
    float* __restrict__ C, const float* __restrict__ bias)
{
    extern __shared__ __align__(16) char sm[];
    const int N = HDIM, K = DIN;
    const int mtile = blockIdx.x * 128, ntile = blockIdx.y * 128;
    const int tid = threadIdx.x, lane = tid & 31, wid = tid >> 5;
    const int warpM = wid & 3, warpN = wid >> 2;
    const uint32_t smBase = smem_u32(sm);

    const int acg = tid & 7;
    const __half* aPh[4]; const __half* aPl[4]; uint32_t aDst[4];
#pragma unroll
    for (int i = 0; i < 4; i++) {
        int row = (tid >> 3) + i * 32;
        size_t off = (size_t)(mtile + row) * K + acg * 4;
        aPh[i] = Ahp + off; aPl[i] = Alp + off;
        aDst[i] = (uint32_t)(row * 80 + acg * 8);
    }
    const __half* bPtr[4]; uint32_t bDst[4];
#pragma unroll
    for (int i = 0; i < 4; i++) {
        int idx = tid + (i << 8);
        int plane = idx >> 9, f = idx & 511;
        int row = f >> 2, cg = f & 3;
        bPtr[i] = (plane ? Blp : Bhp) + (size_t)(ntile + row) * K + cg * 8;
        bDst[i] = (plane ? 30720u : 20480u) + (uint32_t)(row * 80 + cg * 16);
    }

    const int qa = lane >> 3, ra = lane & 7;
    const int lrow = ((qa & 1) << 3) + ra;
    const int lcolB = ((qa >> 1) << 3) * 2;
    const uint32_t aFragOff = (uint32_t)((warpM * 32 + lrow) * 80) + lcolB;
    const uint32_t bFragOff = (uint32_t)((warpN * 64 + lrow) * 80) + lcolB + 20480u;

    float acc[2][8][4];
#pragma unroll
    for (int mt = 0; mt < 2; mt++)
#pragma unroll
        for (int nt = 0; nt < 8; nt++)
#pragma unroll
            for (int q = 0; q < 4; q++) acc[mt][nt][q] = 0.0f;

    const int NC = K >> 5;
    {
        char* base = sm;
#pragma unroll
        for (int i = 0; i < 4; i++) {
            *(uint2*)(base + aDst[i])         = *(const uint2*)aPh[i];
            *(uint2*)(base + 10240 + aDst[i]) = *(const uint2*)aPl[i];
        }
#pragma unroll
        for (int i = 0; i < 4; i++)
            *(uint4*)(base + bDst[i]) = *(const uint4*)bPtr[i];
    }
    __syncthreads();

    for (int c = 0; c < NC; c++) {
        uint2 aRh[4], aRl[4]; uint4 bR[4];
        const bool pf = (c + 1) < NC;
        if (pf) {
            const int kc = (c + 1) << 5;
#pragma unroll
            for (int i = 0; i < 4; i++) {
                aRh[i] = *(const uint2*)(aPh[i] + kc);
                aRl[i] = *(const uint2*)(aPl[i] + kc);
            }
#pragma unroll
            for (int i = 0; i < 4; i++)
                bR[i] = *(const uint4*)(bPtr[i] + kc);
        }
        const uint32_t bb = smBase + (uint32_t)(c & 1) * 40960u;
#pragma unroll
        for (int ks = 0; ks < 2; ks++) {
            const uint32_t kso = ks * 32;
            uint4 ah[2], al[2];
#pragma unroll
            for (int mt = 0; mt < 2; mt++) {
                uint32_t ao = bb + aFragOff + mt * 1280u + kso;
                ah[mt] = ldm4(ao);
                al[mt] = ldm4(ao + 10240u);
            }
            uint32_t bh[8][2], bl[8][2];
#pragma unroll
            for (int np = 0; np < 4; np++) {
                uint32_t bo = bb + bFragOff + np * 1280u + kso;
                uint4 h = ldm4(bo);
                uint4 l = ldm4(bo + 10240u);
                bh[2*np][0] = h.x; bh[2*np][1] = h.z;
                bh[2*np+1][0] = h.y; bh[2*np+1][1] = h.w;
                bl[2*np][0] = l.x; bl[2*np][1] = l.z;
                bl[2*np+1][0] = l.y; bl[2*np+1][1] = l.w;
            }
#pragma unroll
            for (int mt = 0; mt < 2; mt++)
#pragma unroll
                for (int nt = 0; nt < 8; nt++) {
                    mma_fp16(acc[mt][nt], ah[mt], bh[nt][0], bh[nt][1]);
                    mma_fp16(acc[mt][nt], al[mt], bh[nt][0], bh[nt][1]);
                    mma_fp16(acc[mt][nt], ah[mt], bl[nt][0], bl[nt][1]);
                }
        }
        if (pf) {
            char* base = sm + ((c + 1) & 1) * 40960;
#pragma unroll
            for (int i = 0; i < 4; i++) {
                *(uint2*)(base + aDst[i])         = aRh[i];
                *(uint2*)(base + 10240 + aDst[i]) = aRl[i];
            }
#pragma unroll
            for (int i = 0; i < 4; i++)
                *(uint4*)(base + bDst[i]) = bR[i];
        }
        __syncthreads();
    }

    const int g = lane >> 2, tt = lane & 3;
#pragma unroll
    for (int mt = 0; mt < 2; mt++) {
#pragma unroll
        for (int half = 0; half < 2; half++) {
            int rl = mtile + warpM * 32 + mt * 16 + half * 8 + g;
            float* cp = C + (size_t)rl * N;
#pragma unroll
            for (int nt = 0; nt < 8; nt++) {
                int cn = ntile + warpN * 64 + nt * 8 + tt * 2;
                float x0 = acc[mt][nt][half * 2 + 0] + __ldg(bias + cn);
                float x1 = acc[mt][nt][half * 2 + 1] + __ldg(bias + cn + 1);
                *(float2*)(cp + cn) = make_float2(x0, x1);
            }
        }
    }
}

// ---- fused LN+GELU + gate logits + softmax + top4 + renorm ----
__global__ void ln_gate_kernel(const float* __restrict__ g1,
                               const float* __restrict__ lng, const float* __restrict__ lnb,
                               const float* __restrict__ w2, const float* __restrict__ b2,
                               int* __restrict__ tidx, float* __restrict__ tw,
                               int* __restrict__ counts) {
    int row = blockIdx.x, t = threadIdx.x;
    const float* xr = g1 + (size_t)row * HDIM;
    float4 v = *(const float4*)&xr[t * 4];
    float s = v.x + v.y + v.z + v.w;
    float q = v.x * v.x + v.y * v.y + v.z * v.z + v.w * v.w;
#pragma unroll
    for (int o = 16; o; o >>= 1) {
        s += __shfl_down_sync(0xffffffffu, s, o);
        q += __shfl_down_sync(0xffffffffu, q, o);
    }
    __shared__ float ss[8], qq[8];
    int w = t >> 5, l = t & 31;
    if (l == 0) { ss[w] = s; qq[w] = q; }
    __syncthreads();
    if (w == 0) {
        s = (l < 8) ? ss[l] : 0.0f;
        q = (l < 8) ? qq[l] : 0.0f;
#pragma unroll
        for (int o = 4; o; o >>= 1) {
            s += __shfl_down_sync(0xffffffffu, s, o);
            q += __shfl_down_sync(0xffffffffu, q, o);
        }
        if (l == 0) { ss[0] = s; qq[0] = q; }
    }
    __syncthreads();
    float mu  = ss[0] * (1.0f / HDIM);
    float var = qq[0] * (1.0f / HDIM) - mu * mu;
    float r = rsqrtf(var + EPSN);
    float4 gv = *(const float4*)&lng[t * 4];
    float4 bv = *(const float4*)&lnb[t * 4];
    float act[4];
    act[0] = gelu_f((v.x - mu) * r * gv.x + bv.x);
    act[1] = gelu_f((v.y - mu) * r * gv.y + bv.y);
    act[2] = gelu_f((v.z - mu) * r * gv.z + bv.z);
    act[3] = gelu_f((v.w - mu) * r * gv.w + bv.w);

    float part[NEXP];
#pragma unroll
    for (int e = 0; e < NEXP; e++) part[e] = 0.0f;
    int k0 = t * 4;
#pragma unroll
    for (int j = 0; j < 4; j++) {
        const float* wr = w2 + (size_t)(k0 + j) * NEXP;
        float a = act[j];
#pragma unroll
        for (int e = 0; e < NEXP; e++) part[e] += a * wr[e];
    }
#pragma unroll
    for (int e = 0; e < NEXP; e++) {
#pragma unroll
        for (int o = 16; o; o >>= 1)
            part[e] += __shfl_down_sync(0xffffffffu, part[e], o);
    }
    __shared__ float red[8][NEXP];
    if (l == 0) {
#pragma unroll
        for (int e = 0; e < NEXP; e++) red[w][e] = part[e];
    }
    __syncthreads();
    __shared__ float logit[NEXP];
    if (t < NEXP) {
        float sum = 0.0f;
#pragma unroll
        for (int ww = 0; ww < 8; ww++) sum += red[ww][t];
        logit[t] = sum + b2[t];
    }
    __syncthreads();
    if (t == 0) {
        float mx = -1e30f;
        for (int i = 0; i < NEXP; i++) mx = fmaxf(mx, logit[i]);
        float p[NEXP], sum = 0.0f;
        for (int i = 0; i < NEXP; i++) { p[i] = expf(logit[i] - mx); sum += p[i]; }
        float inv = 1.0f / sum;
        bool used[NEXP];
        for (int i = 0; i < NEXP; i++) used[i] = false;
        int idx[KSEL]; float val[KSEL];
        for (int tk = 0; tk < KSEL; tk++) {
            int best = -1; float bvx = -1e30f;
            for (int i = 0; i < NEXP; i++)
                if (!used[i] && p[i] > bvx) { bvx = p[i]; best = i; }
            used[best] = true; idx[tk] = best; val[tk] = bvx * inv;
        }
        float m2 = val[0], e2[KSEL], s2 = 0.0f;
        for (int tk = 0; tk < KSEL; tk++) { e2[tk] = expf(val[tk] - m2); s2 += e2[tk]; }
        float inv2 = 1.0f / s2;
        for (int tk = 0; tk < KSEL; tk++) {
            tidx[row * KSEL + tk] = idx[tk];
            tw[row * KSEL + tk]   = e2[tk] * inv2;
            atomicAdd(&counts[idx[tk]], 1);
        }
    }
}

// ---- dispatch bookkeeping ----
__global__ void reset_kernel(int* __restrict__ counts) {
    if (threadIdx.x < NEXP) counts[threadIdx.x] = 0;
}
__global__ void scan_kernel(const int* __restrict__ counts, int* __restrict__ offsets,
                            int* __restrict__ cursor) {
    if (threadIdx.x == 0) {
        int acc = 0;
        for (int e = 0; e < NEXP; e++) { offsets[e] = acc; cursor[e] = acc; acc += counts[e]; }
        offsets[NEXP] = acc;
    }
}
__global__ void scatter_kernel(const int* __restrict__ tidx, int* __restrict__ cursor,
                               int* __restrict__ rowinfo) {
    int i = blockIdx.x * 256 + threadIdx.x;
    if (i < BTOK * KSEL) {
        int pos = atomicAdd(&cursor[tidx[i]], 1);
        rowinfo[pos] = i;
    }
}

// ---- weighted top-k combine (fp16 in/out) ----
__global__ void combine_kernel(const __half* __restrict__ h2f, const float* __restrict__ tw,
                               __half* __restrict__ ff) {
    int idx = blockIdx.x * 256 + threadIdx.x;
    if (idx < BTOK * HDIM) {
        int b = idx >> 10, h = idx & (HDIM - 1);
        const __half* base = h2f + ((size_t)b * KSEL) * HDIM + h;
        const float* w = tw + b * KSEL;
        float v = w[0] * __half2float(base[0]) + w[1] * __half2float(base[HDIM])
                + w[2] * __half2float(base[2 * HDIM]) + w[3] * __half2float(base[3 * HDIM]);
        ff[idx] = __float2half_rn(v);
    }
}

// ---- final head GEMM [4096,512]x[512,20] ----
__global__ void final_kernel(const float* __restrict__ o1, const float* __restrict__ w2,
                             const float* __restrict__ b2, float* __restrict__ out) {
    int b = blockIdx.x;
    __shared__ float row[512];
    int t = threadIdx.x;
    for (int k = t; k < 512; k += 160) row[k] = o1[(size_t)b * 512 + k];
    __syncthreads();
    int c = t >> 3, sub = t & 7;
    float s = 0.0f;
    for (int k = sub; k < 512; k += 8) s += row[k] * w2[k * NCLS + c];
    s += __shfl_down_sync(0xffffffffu, s, 4);
    s += __shfl_down_sync(0xffffffffu, s, 2);
    s += __shfl_down_sync(0xffffffffu, s, 1);
    if (sub == 0) out[b * NCLS + c] = s + b2[c];
}

// ---- launch ----
extern "C" void kernel_launch(void* const* d_in, const int* in_sizes, int n_in,
                              void* d_out, int out_size) {
    const float* wifi      = (const float*)d_in[0];
    const float* rfid      = (const float*)d_in[1];
    const float* gate_w1   = (const float*)d_in[2];
    const float* gate_b1   = (const float*)d_in[3];
    const float* gate_ln_g = (const float*)d_in[4];
    const float* gate_ln_b = (const float*)d_in[5];
    const float* gate_w2   = (const float*)d_in[6];
    const float* gate_b2   = (const float*)d_in[7];
    const float* exp_w1    = (const float*)d_in[8];
    const float* exp_b1    = (const float*)d_in[9];
    const float* exp_bn1_g = (const float*)d_in[10];
    const float* exp_bn1_b = (const float*)d_in[11];
    const float* exp_bn1_m = (const float*)d_in[12];
    const float* exp_bn1_v = (const float*)d_in[13];
    const float* exp_w2    = (const float*)d_in[14];
    const float* exp_b2    = (const float*)d_in[15];
    const float* exp_bn2_g = (const float*)d_in[16];
    const float* exp_bn2_b = (const float*)d_in[17];
    const float* exp_bn2_m = (const float*)d_in[18];
    const float* exp_bn2_v = (const float*)d_in[19];
    const float* fin_w1    = (const float*)d_in[20];
    const float* fin_b1    = (const float*)d_in[21];
    const float* fin_bn_g  = (const float*)d_in[22];
    const float* fin_bn_b  = (const float*)d_in[23];
    const float* fin_bn_m  = (const float*)d_in[24];
    const float* fin_bn_v  = (const float*)d_in[25];
    const float* fin_w2    = (const float*)d_in[26];
    const float* fin_b2    = (const float*)d_in[27];
    float* out = (float*)d_out;

    float *g1, *tw, *o1;
    int *tidx, *counts, *cursor, *offsets, *rowinfo;
    __half *combh, *combl, *h1f, *h2f, *fusedf, *ew1f, *ew2f, *fw1f, *gw1h, *gw1l;
    cudaGetSymbolAddress((void**)&combh,    g_combh);
    cudaGetSymbolAddress((void**)&combl,    g_combl);
    cudaGetSymbolAddress((void**)&g1,       g_g1);
    cudaGetSymbolAddress((void**)&tidx,     g_tidx);
    cudaGetSymbolAddress((void**)&tw,       g_tw);
    cudaGetSymbolAddress((void**)&counts,   g_counts);
    cudaGetSymbolAddress((void**)&cursor,   g_cursor);
    cudaGetSymbolAddress((void**)&offsets,  g_offsets);
    cudaGetSymbolAddress((void**)&rowinfo,  g_rowinfo);
    cudaGetSymbolAddress((void**)&h1f,      g_h1f);
    cudaGetSymbolAddress((void**)&h2f,      g_h2f);
    cudaGetSymbolAddress((void**)&fusedf,   g_fusedf);
    cudaGetSymbolAddress((void**)&o1,       g_o1);
    cudaGetSymbolAddress((void**)&ew1f,     g_ew1f);
    cudaGetSymbolAddress((void**)&ew2f,     g_ew2f);
    cudaGetSymbolAddress((void**)&fw1f,     g_fw1f);
    cudaGetSymbolAddress((void**)&gw1h,     g_gw1h);
    cudaGetSymbolAddress((void**)&gw1l,     g_gw1l);

    cudaFuncSetAttribute(w_gemm<true, true, false, true, true>,
                         cudaFuncAttributeMaxDynamicSharedMemorySize, WG_SMEM);
    cudaFuncSetAttribute(w_gemm<true, false, true, true, true>,
                         cudaFuncAttributeMaxDynamicSharedMemorySize, WG_SMEM);
    cudaFuncSetAttribute(w_gemm<false, false, false, true, false>,
                         cudaFuncAttributeMaxDynamicSharedMemorySize, WG_SMEM);
    cudaFuncSetAttribute(gate_hmma,
                         cudaFuncAttributeMaxDynamicSharedMemorySize, GG_SMEM);

    // weight transpose+convert (pure bandwidth)
    wsplit_kernel<<<dim3(32, 16, NEXP), dim3(32, 8)>>>(exp_w1, ew1f, DIN, HDIM);
    wsplit_kernel<<<dim3(32, 32, NEXP), dim3(32, 8)>>>(exp_w2, ew2f, HDIM, HDIM);
    wsplit_kernel<<<dim3(16, 32, 1),    dim3(32, 8)>>>(fin_w1, fw1f, HDIM, 512);
    wsplit2_kernel<<<dim3(32, 16), dim3(32, 8)>>>(gate_w1, gw1h, gw1l, DIN, HDIM);

    // 1. concat (fp16 hi/lo planes)
    concat_kernel<<<(BTOK * DIN + 255) / 256, 256>>>(wifi, rfid, combh, combl);
    // 2. gate GEMM1 (fp16 3-pass, near-fp32)
    gate_hmma<<<dim3(32, 8), 256, GG_SMEM>>>(combh, combl, gw1h, gw1l, g1, gate_b1);
    // 3+4. fused LN+GELU + gate logits + top4
    reset_kernel<<<1, 32>>>(counts);
    ln_gate_kernel<<<BTOK, 256>>>(g1, gate_ln_g, gate_ln_b, gate_w2, gate_b2,
                                  tidx, tw, counts);
    // 5. dispatch
    scan_kernel<<<1, 1>>>(counts, offsets, cursor);
    scatter_kernel<<<(BTOK * KSEL + 255) / 256, 256>>>(tidx, cursor, rowinfo);
    // 6. expert GEMM1 (gather, BN1+GELU, fp16 output)
    w_gemm<true, true, false, true, true><<<dim3(32, 8, NEXP), 256, WG_SMEM>>>(
        combh, ew1f, nullptr, h1f, 0, HDIM, DIN,
        offsets, rowinfo, exp_b1, exp_bn1_g, exp_bn1_b, exp_bn1_m, exp_bn1_v);
    // 7. expert GEMM2 (scatter, BN2+GELU, fp16 output)
    w_gemm<true, false, true, true, true><<<dim3(32, 8, NEXP), 256, WG_SMEM>>>(
        h1f, ew2f, nullptr, h2f, 0, HDIM, HDIM,
        offsets, rowinfo, exp_b2, exp_bn2_g, exp_bn2_b, exp_bn2_m, exp_bn2_v);
    // 8. combine -> fp16 plane
    combine_kernel<<<(BTOK * HDIM + 255) / 256, 256>>>(h2f, tw, fusedf);
    // 9. final GEMM1 (BN+GELU, fp32 output)
    w_gemm<false, false, false, true, false><<<dim3(32, 4, 1), 256, WG_SMEM>>>(
        fusedf, fw1f, o1, nullptr, BTOK, 512, HDIM,
        nullptr, nullptr, fin_b1, fin_bn_g, fin_bn_b, fin_bn_m, fin_bn_v);
    // 10. head
    final_kernel<<<BTOK, 160>>>(o1, fin_w2, fin_b2, out);
}

// round 15
// speedup vs baseline: 1.3977x; 1.3977x over previous
#include <cuda_runtime.h>
#include <cuda_fp16.h>
#include <math.h>
#include <stdint.h>

#define BTOK 4096
#define DIN  512
#define HDIM 1024
#define NEXP 16
#define KSEL 4
#define NCLS 20
#define EPSN 1e-5f

// ---- device scratch (no allocation allowed) ----
__device__ __half g_combh[BTOK * DIN];
__device__ __half g_combl[BTOK * DIN];
__device__ float  g_g1[BTOK * HDIM];
__device__ int    g_tidx[BTOK * KSEL];
__device__ float  g_tw[BTOK * KSEL];
__device__ int    g_counts[NEXP];
__device__ int    g_cursor[NEXP];
__device__ int    g_offsets[NEXP + 1];
__device__ int    g_rowinfo[BTOK * KSEL];
__device__ __half g_h1f[BTOK * KSEL * HDIM];
__device__ __half g_h2f[BTOK * KSEL * HDIM];
__device__ __half g_fusedf[BTOK * HDIM];
__device__ float  g_o1[BTOK * 512];
__device__ __half g_ew1f[NEXP * DIN * HDIM];
__device__ __half g_ew2f[NEXP * HDIM * HDIM];
__device__ __half g_fw1f[HDIM * 512];
__device__ __half g_gw1h[DIN * HDIM];
__device__ __half g_gw1l[DIN * HDIM];

__device__ __forceinline__ float gelu_f(float x) {
    return 0.5f * x * (1.0f + erff(x * 0.70710678118654752440f));
}
__device__ __forceinline__ uint32_t smem_u32(const void* p) {
    uint32_t a;
    asm("{ .reg .u64 t; cvta.to.shared.u64 t, %1; cvt.u32.u64 %0, t; }" : "=r"(a) : "l"(p));
    return a;
}
__device__ __forceinline__ uint4 ldm4(uint32_t addr) {
    uint4 r;
    asm volatile("ldmatrix.sync.aligned.m8n8.x4.shared.b16 {%0,%1,%2,%3}, [%4];"
                 : "=r"(r.x), "=r"(r.y), "=r"(r.z), "=r"(r.w) : "r"(addr));
    return r;
}
__device__ __forceinline__ void mma_fp16(float* c, const uint4& a, uint32_t b0, uint32_t b1) {
    asm volatile(
        "mma.sync.aligned.m16n8k16.row.col.f32.f16.f16.f32 "
        "{%0,%1,%2,%3}, {%4,%5,%6,%7}, {%8,%9}, {%0,%1,%2,%3};"
        : "+f"(c[0]), "+f"(c[1]), "+f"(c[2]), "+f"(c[3])
        : "r"(a.x), "r"(a.y), "r"(a.z), "r"(a.w), "r"(b0), "r"(b1));
}
__device__ __forceinline__ uint32_t pkh(__half a, __half b) {
    return (uint32_t)__half_as_ushort(a) | ((uint32_t)__half_as_ushort(b) << 16);
}
__device__ __forceinline__ void split2h(float x, __half& h, __half& l) {
    h = __float2half_rn(x);
    l = __float2half_rn(x - __half2float(h));
}

// ---- concat -> fp16 hi/lo planes ----
__global__ void concat_kernel(const float* __restrict__ wifi, const float* __restrict__ rfid,
                              __half* __restrict__ ch, __half* __restrict__ cl) {
    int i = blockIdx.x * 256 + threadIdx.x;
    if (i < BTOK * DIN) {
        int b = i >> 9, c = i & 511;
        float v = (c < 256) ? wifi[b * 256 + c] : rfid[b * 256 + (c - 256)];
        __half h, l; split2h(v, h, l);
        ch[i] = h; cl[i] = l;
    }
}

// ---- weight transpose + fp16 convert (1 plane): W[e,K,N] -> T[e,N,K] ----
__global__ void wsplit_kernel(const float* __restrict__ W, __half* __restrict__ Tf,
                              int K, int N) {
    __shared__ float tile[32][33];
    size_t base = (size_t)blockIdx.z * K * N;
    int k0 = blockIdx.y * 32, n0 = blockIdx.x * 32;
    int tx = threadIdx.x, ty = threadIdx.y;
#pragma unroll
    for (int i = 0; i < 32; i += 8)
        tile[ty + i][tx] = W[base + (size_t)(k0 + ty + i) * N + n0 + tx];
    __syncthreads();
#pragma unroll
    for (int i = 0; i < 32; i += 8) {
        int n = n0 + ty + i, k = k0 + tx;
        Tf[base + (size_t)n * K + k] = __float2half_rn(tile[tx][ty + i]);
    }
}

// ---- weight transpose + fp16 hi/lo split (2 planes) ----
__global__ void wsplit2_kernel(const float* __restrict__ W,
                               __half* __restrict__ Th, __half* __restrict__ Tl,
                               int K, int N) {
    __shared__ float tile[32][33];
    int k0 = blockIdx.y * 32, n0 = blockIdx.x * 32;
    int tx = threadIdx.x, ty = threadIdx.y;
#pragma unroll
    for (int i = 0; i < 32; i += 8)
        tile[ty + i][tx] = W[(size_t)(k0 + ty + i) * N + n0 + tx];
    __syncthreads();
#pragma unroll
    for (int i = 0; i < 32; i += 8) {
        int n = n0 + ty + i, k = k0 + tx;
        __half h, l; split2h(tile[tx][ty + i], h, l);
        Th[(size_t)n * K + k] = h;
        Tl[(size_t)n * K + k] = l;
    }
}

// ---------------------------------------------------------------------------
// fp16 1-pass HMMA GEMM (R11 mainloop: k-chunk 32, register prefetch, occ 2).
// ---------------------------------------------------------------------------
static constexpr int WG_SMEM = 2 * 20480;

template<bool SEG, bool GATHER, bool SCATTER, bool BN, bool OUTS>
__global__ void __launch_bounds__(256, 2) w_gemm(
    const __half* __restrict__ Ap, const __half* __restrict__ Bp,
    float* __restrict__ C, __half* __restrict__ Cf,
    int Mfixed, int N, int K,
    const int* __restrict__ offsets, const int* __restrict__ rowinfo,
    const float* __restrict__ bias,
    const float* __restrict__ bng, const float* __restrict__ bnb,
    const float* __restrict__ bnm, const float* __restrict__ bnv)
{
    extern __shared__ __align__(16) char sm[];
    int m0 = 0, M = Mfixed;
    if (SEG) {
        int e = blockIdx.z;
        m0 = offsets[e];
        M  = offsets[e + 1] - m0;
        Bp += (size_t)e * K * N;
        bias += (size_t)e * N;
        if (BN) { bng += (size_t)e * N; bnb += (size_t)e * N;
                  bnm += (size_t)e * N; bnv += (size_t)e * N; }
    }
    const int mtile = blockIdx.x * 128;
    if (mtile >= M) return;
    const int ntile = blockIdx.y * 128;

    const int tid = threadIdx.x, lane = tid & 31, wid = tid >> 5;
    const int warpM = wid & 3, warpN = wid >> 2;
    const uint32_t smBase = smem_u32(sm);

    const int acg = tid & 7;
    const __half* aP[4]; bool aval[4]; uint32_t aDst[4];
#pragma unroll
    for (int i = 0; i < 4; i++) {
        int row = (tid >> 3) + i * 32;
        bool v = (mtile + row) < M;
        aval[i] = v;
        int tok = 0;
        if (v) { int gr = m0 + mtile + row; tok = GATHER ? (rowinfo[gr] >> 2) : gr; }
        aP[i] = Ap + (size_t)tok * K + acg * 4;
        aDst[i] = (uint32_t)(row * 80 + acg * 8);
    }
    const __half* bPtr[2]; uint32_t bDst[2];
#pragma unroll
    for (int i = 0; i < 2; i++) {
        int idx = tid + (i << 8);
        int row = idx >> 2, cg = idx & 3;
        bPtr[i] = Bp + (size_t)(ntile + row) * K + cg * 8;
        bDst[i] = 10240u + (uint32_t)(row * 80 + cg * 16);
    }

    const int qa = lane >> 3, ra = lane & 7;
    const int lrow = ((qa & 1) << 3) + ra;
    const int lcolB = ((qa >> 1) << 3) * 2;
    const uint32_t aFragOff = (uint32_t)((warpM * 32 + lrow) * 80) + lcolB;
    const uint32_t bFragOff = (uint32_t)((warpN * 64 + lrow) * 80) + lcolB + 10240u;

    float acc[2][8][4];
#pragma unroll
    for (int mt = 0; mt < 2; mt++)
#pragma unroll
        for (int nt = 0; nt < 8; nt++)
#pragma unroll
            for (int q = 0; q < 4; q++) acc[mt][nt][q] = 0.0f;

    const int NC = K >> 5;
    const uint2 z2 = make_uint2(0u, 0u);

    {
        char* base = sm;
#pragma unroll
        for (int i = 0; i < 4; i++)
            *(uint2*)(base + aDst[i]) = aval[i] ? *(const uint2*)aP[i] : z2;
#pragma unroll
        for (int i = 0; i < 2; i++)
            *(uint4*)(base + bDst[i]) = *(const uint4*)bPtr[i];
    }
    __syncthreads();

    for (int c = 0; c < NC; c++) {
        uint2 aR[4]; uint4 bR[2];
        const bool pf = (c + 1) < NC;
        if (pf) {
            const int kc = (c + 1) << 5;
#pragma unroll
            for (int i = 0; i < 4; i++)
                aR[i] = aval[i] ? *(const uint2*)(aP[i] + kc) : z2;
#pragma unroll
            for (int i = 0; i < 2; i++)
                bR[i] = *(const uint4*)(bPtr[i] + kc);
        }
        const uint32_t bb = smBase + (uint32_t)(c & 1) * 20480u;
#pragma unroll
        for (int ks = 0; ks < 2; ks++) {
            const uint32_t kso = ks * 32;
            uint4 ah[2];
#pragma unroll
            for (int mt = 0; mt < 2; mt++)
                ah[mt] = ldm4(bb + aFragOff + mt * 1280u + kso);
            uint32_t bf[8][2];
#pragma unroll
            for (int np = 0; np < 4; np++) {
                uint4 h = ldm4(bb + bFragOff + np * 1280u + kso);
                bf[2*np][0] = h.x; bf[2*np][1] = h.z;
                bf[2*np+1][0] = h.y; bf[2*np+1][1] = h.w;
            }
#pragma unroll
            for (int mt = 0; mt < 2; mt++)
#pragma unroll
                for (int nt = 0; nt < 8; nt++)
                    mma_fp16(acc[mt][nt], ah[mt], bf[nt][0], bf[nt][1]);
        }
        if (pf) {
            char* base = sm + ((c + 1) & 1) * 20480;
#pragma unroll
            for (int i = 0; i < 4; i++)
                *(uint2*)(base + aDst[i]) = aR[i];
#pragma unroll
            for (int i = 0; i < 2; i++)
                *(uint4*)(base + bDst[i]) = bR[i];
        }
        __syncthreads();
    }

    const int g = lane >> 2, tt = lane & 3;
#pragma unroll
    for (int mt = 0; mt < 2; mt++) {
#pragma unroll
        for (int half = 0; half < 2; half++) {
            int rl = mtile + warpM * 32 + mt * 16 + half * 8 + g;
            if (rl < M) {
                int gr = m0 + rl;
                int crow = SCATTER ? rowinfo[gr] : gr;
                size_t rowoff = (size_t)crow * N;
#pragma unroll
                for (int nt = 0; nt < 8; nt++) {
                    int cn = ntile + warpN * 64 + nt * 8 + tt * 2;
                    float x0 = acc[mt][nt][half * 2 + 0] + __ldg(bias + cn);
                    float x1 = acc[mt][nt][half * 2 + 1] + __ldg(bias + cn + 1);
                    if (BN) {
                        x0 = gelu_f((x0 - __ldg(bnm + cn)) * rsqrtf(__ldg(bnv + cn) + EPSN)
                                    * __ldg(bng + cn) + __ldg(bnb + cn));
                        x1 = gelu_f((x1 - __ldg(bnm + cn + 1)) * rsqrtf(__ldg(bnv + cn + 1) + EPSN)
                                    * __ldg(bng + cn + 1) + __ldg(bnb + cn + 1));
                    }
                    if (OUTS) {
                        *(uint32_t*)(Cf + rowoff + cn) =
                            pkh(__float2half_rn(x0), __float2half_rn(x1));
                    } else {
                        *(float2*)(C + rowoff + cn) = make_float2(x0, x1);
                    }
                }
            }
        }
    }
}

// ---------------------------------------------------------------------------
// Gate GEMM: fp16 3-pass (AhBh + AlBh + AhBl), near-fp32. (R11 version)
// ---------------------------------------------------------------------------
static constexpr int GG_SMEM = 2 * 40960;

__global__ void __launch_bounds__(256, 1) gate_hmma(
    const __half* __restrict__ Ahp, const __half* __restrict__ Alp,
    const __half* __restrict__ Bhp, const __half* __restrict__ Blp,
    float* __restrict__ C, const float* __restrict__ bias)
{
    extern __shared__ __align__(16) char sm[];
    const int N = HDIM, K = DIN;
    const int mtile = blockIdx.x * 128, ntile = blockIdx.y * 128;
    const int tid = threadIdx.x, lane = tid & 31, wid = tid >> 5;
    const int warpM = wid & 3, warpN = wid >> 2;
    const uint32_t smBase = smem_u32(sm);

    const int acg = tid & 7;
    const __half* aPh[4]; const __half* aPl[4]; uint32_t aDst[4];
#pragma unroll
    for (int i = 0; i < 4; i++) {
        int row = (tid >> 3) + i * 32;
        size_t off = (size_t)(mtile + row) * K + acg * 4;
        aPh[i] = Ahp + off; aPl[i] = Alp + off;
        aDst[i] = (uint32_t)(row * 80 + acg * 8);
    }
    const __half* bPtr[4]; uint32_t bDst[4];
#pragma unroll
    for (int i = 0; i < 4; i++) {
        int idx = tid + (i << 8);
        int plane = idx >> 9, f = idx & 511;
        int row = f >> 2, cg = f & 3;
        bPtr[i] = (plane ? Blp : Bhp) + (size_t)(ntile + row) * K + cg * 8;
        bDst[i] = (plane ? 30720u : 20480u) + (uint32_t)(row * 80 + cg * 16);
    }

    const int qa = lane >> 3, ra = lane & 7;
    const int lrow = ((qa & 1) << 3) + ra;
    const int lcolB = ((qa >> 1) << 3) * 2;
    const uint32_t aFragOff = (uint32_t)((warpM * 32 + lrow) * 80) + lcolB;
    const uint32_t bFragOff = (uint32_t)((warpN * 64 + lrow) * 80) + lcolB + 20480u;

    float acc[2][8][4];
#pragma unroll
    for (int mt = 0; mt < 2; mt++)
#pragma unroll
        for (int nt = 0; nt < 8; nt++)
#pragma unroll
            for (int q = 0; q < 4; q++) acc[mt][nt][q] = 0.0f;

    const int NC = K >> 5;
    {
        char* base = sm;
#pragma unroll
        for (int i = 0; i < 4; i++) {
            *(uint2*)(base + aDst[i])         = *(const uint2*)aPh[i];
            *(uint2*)(base + 10240 + aDst[i]) = *(const uint2*)aPl[i];
        }
#pragma unroll
        for (int i = 0; i < 4; i++)
            *(uint4*)(base + bDst[i]) = *(const uint4*)bPtr[i];
    }
    __syncthreads();

    for (int c = 0; c < NC; c++) {
        uint2 aRh[4], aRl[4]; uint4 bR[4];
        const bool pf = (c + 1) < NC;
        if (pf) {
            const int kc = (c + 1) << 5;
#pragma unroll
            for (int i = 0; i < 4; i++) {
                aRh[i] = *(const uint2*)(aPh[i] + kc);
                aRl[i] = *(const uint2*)(aPl[i] + kc);
            }
#pragma unroll
            for (int i = 0; i < 4; i++)
                bR[i] = *(const uint4*)(bPtr[i] + kc);
        }
        const uint32_t bb = smBase + (uint32_t)(c & 1) * 40960u;
#pragma unroll
        for (int ks = 0; ks < 2; ks++) {
            const uint32_t kso = ks * 32;
            uint4 ah[2], al[2];
#pragma unroll
            for (int mt = 0; mt < 2; mt++) {
                uint32_t ao = bb + aFragOff + mt * 1280u + kso;
                ah[mt] = ldm4(ao);
                al[mt] = ldm4(ao + 10240u);
            }
            uint32_t bh[8][2], bl[8][2];
#pragma unroll
            for (int np = 0; np < 4; np++) {
                uint32_t bo = bb + bFragOff + np * 1280u + kso;
                uint4 h = ldm4(bo);
                uint4 l = ldm4(bo + 10240u);
                bh[2*np][0] = h.x; bh[2*np][1] = h.z;
                bh[2*np+1][0] = h.y; bh[2*np+1][1] = h.w;
                bl[2*np][0] = l.x; bl[2*np][1] = l.z;
                bl[2*np+1][0] = l.y; bl[2*np+1][1] = l.w;
            }
#pragma unroll
            for (int mt = 0; mt < 2; mt++)
#pragma unroll
                for (int nt = 0; nt < 8; nt++) {
                    mma_fp16(acc[mt][nt], ah[mt], bh[nt][0], bh[nt][1]);
                    mma_fp16(acc[mt][nt], al[mt], bh[nt][0], bh[nt][1]);
                    mma_fp16(acc[mt][nt], ah[mt], bl[nt][0], bl[nt][1]);
                }
        }
        if (pf) {
            char* base = sm + ((c + 1) & 1) * 40960;
#pragma unroll
            for (int i = 0; i < 4; i++) {
                *(uint2*)(base + aDst[i])         = aRh[i];
                *(uint2*)(base + 10240 + aDst[i]) = aRl[i];
            }
#pragma unroll
            for (int i = 0; i < 4; i++)
                *(uint4*)(base + bDst[i]) = bR[i];
        }
        __syncthreads();
    }

    const int g = lane >> 2, tt = lane & 3;
#pragma unroll
    for (int mt = 0; mt < 2; mt++) {
#pragma unroll
        for (int half = 0; half < 2; half++) {
            int rl = mtile + warpM * 32 + mt * 16 + half * 8 + g;
            float* cp = C + (size_t)rl * N;
#pragma unroll
            for (int nt = 0; nt < 8; nt++) {
                int cn = ntile + warpN * 64 + nt * 8 + tt * 2;
                float x0 = acc[mt][nt][half * 2 + 0] + __ldg(bias + cn);
                float x1 = acc[mt][nt][half * 2 + 1] + __ldg(bias + cn + 1);
                *(float2*)(cp + cn) = make_float2(x0, x1);
            }
        }
    }
}

// ---- LayerNorm + GELU (in place, row=1024) — R11 version ----
__global__ void ln_gelu_kernel(float* __restrict__ x, const float* __restrict__ g,
                               const float* __restrict__ b) {
    int row = blockIdx.x;
    float* xr = x + (size_t)row * HDIM;
    int t = threadIdx.x;
    float4 v = *(float4*)&xr[t * 4];
    float s = v.x + v.y + v.z + v.w;
    float q = v.x * v.x + v.y * v.y + v.z * v.z + v.w * v.w;
#pragma unroll
    for (int o = 16; o; o >>= 1) {
        s += __shfl_down_sync(0xffffffffu, s, o);
        q += __shfl_down_sync(0xffffffffu, q, o);
    }
    __shared__ float ss[8], qq[8];
    int w = t >> 5, l = t & 31;
    if (l == 0) { ss[w] = s; qq[w] = q; }
    __syncthreads();
    if (w == 0) {
        s = (l < 8) ? ss[l] : 0.0f;
        q = (l < 8) ? qq[l] : 0.0f;
#pragma unroll
        for (int o = 4; o; o >>= 1) {
            s += __shfl_down_sync(0xffffffffu, s, o);
            q += __shfl_down_sync(0xffffffffu, q, o);
        }
        if (l == 0) { ss[0] = s; qq[0] = q; }
    }
    __syncthreads();
    float mu  = ss[0] * (1.0f / HDIM);
    float var = qq[0] * (1.0f / HDIM) - mu * mu;
    float r = rsqrtf(var + EPSN);
    float4 gv = *(const float4*)&g[t * 4];
    float4 bv = *(const float4*)&b[t * 4];
    v.x = gelu_f((v.x - mu) * r * gv.x + bv.x);
    v.y = gelu_f((v.y - mu) * r * gv.y + bv.y);
    v.z = gelu_f((v.z - mu) * r * gv.z + bv.z);
    v.w = gelu_f((v.w - mu) * r * gv.w + bv.w);
    *(float4*)&xr[t * 4] = v;
}

// ---- gate logits + softmax + top4 + renorm — R11 version ----
__global__ void gate_topk_kernel(const float* __restrict__ g1, const float* __restrict__ w2,
                                 const float* __restrict__ b2, int* __restrict__ tidx,
                                 float* __restrict__ tw, int* __restrict__ counts) {
    int b = blockIdx.x, t = threadIdx.x;
    int e = t >> 3, sub = t & 7;
    const float* row = g1 + (size_t)b * HDIM;
    float s = 0.0f;
    for (int k = sub; k < HDIM; k += 8) s += row[k] * w2[k * NEXP + e];
    s += __shfl_down_sync(0xffffffffu, s, 4);
    s += __shfl_down_sync(0xffffffffu, s, 2);
    s += __shfl_down_sync(0xffffffffu, s, 1);
    __shared__ float logit[NEXP];
    if (sub == 0) logit[e] = s + b2[e];
    __syncthreads();
    if (t == 0) {
        float mx = -1e30f;
        for (int i = 0; i < NEXP; i++) mx = fmaxf(mx, logit[i]);
        float p[NEXP], sum = 0.0f;
        for (int i = 0; i < NEXP; i++) { p[i] = expf(logit[i] - mx); sum += p[i]; }
        float inv = 1.0f / sum;
        bool used[NEXP];
        for (int i = 0; i < NEXP; i++) used[i] = false;
        int idx[KSEL]; float val[KSEL];
        for (int tk = 0; tk < KSEL; tk++) {
            int best = -1; float bv = -1e30f;
            for (int i = 0; i < NEXP; i++)
                if (!used[i] && p[i] > bv) { bv = p[i]; best = i; }
            used[best] = true; idx[tk] = best; val[tk] = bv * inv;
        }
        float m2 = val[0], e2[KSEL], s2 = 0.0f;
        for (int tk = 0; tk < KSEL; tk++) { e2[tk] = expf(val[tk] - m2); s2 += e2[tk]; }
        float inv2 = 1.0f / s2;
        for (int tk = 0; tk < KSEL; tk++) {
            tidx[b * KSEL + tk] = idx[tk];
            tw[b * KSEL + tk]   = e2[tk] * inv2;
            atomicAdd(&counts[idx[tk]], 1);
        }
    }
}

// ---- dispatch bookkeeping ----
__global__ void reset_kernel(int* __restrict__ counts) {
    if (threadIdx.x < NEXP) counts[threadIdx.x] = 0;
}
__global__ void scan_kernel(const int* __restrict__ counts, int* __restrict__ offsets,
                            int* __restrict__ cursor) {
    if (threadIdx.x == 0) {
        int acc = 0;
        for (int e = 0; e < NEXP; e++) { offsets[e] = acc; cursor[e] = acc; acc += counts[e]; }
        offsets[NEXP] = acc;
    }
}
__global__ void scatter_kernel(const int* __restrict__ tidx, int* __restrict__ cursor,
                               int* __restrict__ rowinfo) {
    int i = blockIdx.x * 256 + threadIdx.x;
    if (i < BTOK * KSEL) {
        int pos = atomicAdd(&cursor[tidx[i]], 1);
        rowinfo[pos] = i;
    }
}

// ---- weighted top-k combine (fp16 in/out) ----
__global__ void combine_kernel(const __half* __restrict__ h2f, const float* __restrict__ tw,
                               __half* __restrict__ ff) {
    int idx = blockIdx.x * 256 + threadIdx.x;
    if (idx < BTOK * HDIM) {
        int b = idx >> 10, h = idx & (HDIM - 1);
        const __half* base = h2f + ((size_t)b * KSEL) * HDIM + h;
        const float* w = tw + b * KSEL;
        float v = w[0] * __half2float(base[0]) + w[1] * __half2float(base[HDIM])
                + w[2] * __half2float(base[2 * HDIM]) + w[3] * __half2float(base[3 * HDIM]);
        ff[idx] = __float2half_rn(v);
    }
}

// ---- final head GEMM [4096,512]x[512,20] ----
__global__ void final_kernel(const float* __restrict__ o1, const float* __restrict__ w2,
                             const float* __restrict__ b2, float* __restrict__ out) {
    int b = blockIdx.x;
    __shared__ float row[512];
    int t = threadIdx.x;
    for (int k = t; k < 512; k += 160) row[k] = o1[(size_t)b * 512 + k];
    __syncthreads();
    int c = t >> 3, sub = t & 7;
    float s = 0.0f;
    for (int k = sub; k < 512; k += 8) s += row[k] * w2[k * NCLS + c];
    s += __shfl_down_sync(0xffffffffu, s, 4);
    s += __shfl_down_sync(0xffffffffu, s, 2);
    s += __shfl_down_sync(0xffffffffu, s, 1);
    if (sub == 0) out[b * NCLS + c] = s + b2[c];
}

// ---- launch ----
extern "C" void kernel_launch(void* const* d_in, const int* in_sizes, int n_in,
                              void* d_out, int out_size) {
    const float* wifi      = (const float*)d_in[0];
    const float* rfid      = (const float*)d_in[1];
    const float* gate_w1   = (const float*)d_in[2];
    const float* gate_b1   = (const float*)d_in[3];
    const float* gate_ln_g = (const float*)d_in[4];
    const float* gate_ln_b = (const float*)d_in[5];
    const float* gate_w2   = (const float*)d_in[6];
    const float* gate_b2   = (const float*)d_in[7];
    const float* exp_w1    = (const float*)d_in[8];
    const float* exp_b1    = (const float*)d_in[9];
    const float* exp_bn1_g = (const float*)d_in[10];
    const float* exp_bn1_b = (const float*)d_in[11];
    const float* exp_bn1_m = (const float*)d_in[12];
    const float* exp_bn1_v = (const float*)d_in[13];
    const float* exp_w2    = (const float*)d_in[14];
    const float* exp_b2    = (const float*)d_in[15];
    const float* exp_bn2_g = (const float*)d_in[16];
    const float* exp_bn2_b = (const float*)d_in[17];
    const float* exp_bn2_m = (const float*)d_in[18];
    const float* exp_bn2_v = (const float*)d_in[19];
    const float* fin_w1    = (const float*)d_in[20];
    const float* fin_b1    = (const float*)d_in[21];
    const float* fin_bn_g  = (const float*)d_in[22];
    const float* fin_bn_b  = (const float*)d_in[23];
    const float* fin_bn_m  = (const float*)d_in[24];
    const float* fin_bn_v  = (const float*)d_in[25];
    const float* fin_w2    = (const float*)d_in[26];
    const float* fin_b2    = (const float*)d_in[27];
    float* out = (float*)d_out;

    float *g1, *tw, *o1;
    int *tidx, *counts, *cursor, *offsets, *rowinfo;
    __half *combh, *combl, *h1f, *h2f, *fusedf, *ew1f, *ew2f, *fw1f, *gw1h, *gw1l;
    cudaGetSymbolAddress((void**)&combh,    g_combh);
    cudaGetSymbolAddress((void**)&combl,    g_combl);
    cudaGetSymbolAddress((void**)&g1,       g_g1);
    cudaGetSymbolAddress((void**)&tidx,     g_tidx);
    cudaGetSymbolAddress((void**)&tw,       g_tw);
    cudaGetSymbolAddress((void**)&counts,   g_counts);
    cudaGetSymbolAddress((void**)&cursor,   g_cursor);
    cudaGetSymbolAddress((void**)&offsets,  g_offsets);
    cudaGetSymbolAddress((void**)&rowinfo,  g_rowinfo);
    cudaGetSymbolAddress((void**)&h1f,      g_h1f);
    cudaGetSymbolAddress((void**)&h2f,      g_h2f);
    cudaGetSymbolAddress((void**)&fusedf,   g_fusedf);
    cudaGetSymbolAddress((void**)&o1,       g_o1);
    cudaGetSymbolAddress((void**)&ew1f,     g_ew1f);
    cudaGetSymbolAddress((void**)&ew2f,     g_ew2f);
    cudaGetSymbolAddress((void**)&fw1f,     g_fw1f);
    cudaGetSymbolAddress((void**)&gw1h,     g_gw1h);
    cudaGetSymbolAddress((void**)&gw1l,     g_gw1l);

    cudaFuncSetAttribute(w_gemm<true, true, false, true, true>,
                         cudaFuncAttributeMaxDynamicSharedMemorySize, WG_SMEM);
    cudaFuncSetAttribute(w_gemm<true, false, true, true, true>,
                         cudaFuncAttributeMaxDynamicSharedMemorySize, WG_SMEM);
    cudaFuncSetAttribute(w_gemm<false, false, false, true, false>,
                         cudaFuncAttributeMaxDynamicSharedMemorySize, WG_SMEM);
    cudaFuncSetAttribute(gate_hmma,
                         cudaFuncAttributeMaxDynamicSharedMemorySize, GG_SMEM);

    // weight transpose+convert (pure bandwidth)
    wsplit_kernel<<<dim3(32, 16, NEXP), dim3(32, 8)>>>(exp_w1, ew1f, DIN, HDIM);
    wsplit_kernel<<<dim3(32, 32, NEXP), dim3(32, 8)>>>(exp_w2, ew2f, HDIM, HDIM);
    wsplit_kernel<<<dim3(16, 32, 1),    dim3(32, 8)>>>(fin_w1, fw1f, HDIM, 512);
    wsplit2_kernel<<<dim3(32, 16), dim3(32, 8)>>>(gate_w1, gw1h, gw1l, DIN, HDIM);

    // 1. concat (fp16 hi/lo planes)
    concat_kernel<<<(BTOK * DIN + 255) / 256, 256>>>(wifi, rfid, combh, combl);
    // 2. gate GEMM1 (fp16 3-pass, near-fp32)
    gate_hmma<<<dim3(32, 8), 256, GG_SMEM>>>(combh, combl, gw1h, gw1l, g1, gate_b1);
    // 3. LN + GELU (in place on g1)
    ln_gelu_kernel<<<BTOK, 256>>>(g1, gate_ln_g, gate_ln_b);
    // 4. gate top-4
    reset_kernel<<<1, 32>>>(counts);
    gate_topk_kernel<<<BTOK, 128>>>(g1, gate_w2, gate_b2, tidx, tw, counts);
    // 5. dispatch
    scan_kernel<<<1, 1>>>(counts, offsets, cursor);
    scatter_kernel<<<(BTOK * KSEL + 255) / 256, 256>>>(tidx, cursor, rowinfo);
    // 6. expert GEMM1 (gather, BN1+GELU, fp16 output)
    w_gemm<true, true, false, true, true><<<dim3(32, 8, NEXP), 256, WG_SMEM>>>(
        combh, ew1f, nullptr, h1f, 0, HDIM, DIN,
        offsets, rowinfo, exp_b1, exp_bn1_g, exp_bn1_b, exp_bn1_m, exp_bn1_v);
    // 7. expert GEMM2 (scatter, BN2+GELU, fp16 output)
    w_gemm<true, false, true, true, true><<<dim3(32, 8, NEXP), 256, WG_SMEM>>>(
        h1f, ew2f, nullptr, h2f, 0, HDIM, HDIM,
        offsets, rowinfo, exp_b2, exp_bn2_g, exp_bn2_b, exp_bn2_m, exp_bn2_v);
    // 8. combine -> fp16 plane
    combine_kernel<<<(BTOK * HDIM + 255) / 256, 256>>>(h2f, tw, fusedf);
    // 9. final GEMM1 (BN+GELU, fp32 output)
    w_gemm<false, false, false, true, false><<<dim3(32, 4, 1), 256, WG_SMEM>>>(
        fusedf, fw1f, o1, nullptr, BTOK, 512, HDIM,
        nullptr, nullptr, fin_b1, fin_bn_g, fin_bn_b, fin_bn_m, fin_bn_v);
    // 10. head
    final_kernel<<<BTOK, 160>>>(o1, fin_w2, fin_b2, out);
}

// round 17
// speedup vs baseline: 1.4414x; 1.0312x over previous
#include <cuda_runtime.h>
#include <cuda_fp16.h>
#include <math.h>
#include <stdint.h>

#define BTOK 4096
#define DIN  512
#define HDIM 1024
#define NEXP 16
#define KSEL 4
#define NCLS 20
#define EPSN 1e-5f

// ---- device scratch (no allocation allowed) ----
__device__ __half g_combh[BTOK * DIN];
__device__ __half g_combl[BTOK * DIN];
__device__ float  g_g1[BTOK * HDIM];
__device__ int    g_tidx[BTOK * KSEL];
__device__ float  g_tw[BTOK * KSEL];
__device__ int    g_counts[NEXP];
__device__ int    g_cursor[NEXP];
__device__ int    g_offsets[NEXP + 1];
__device__ int    g_rowinfo[BTOK * KSEL];
__device__ __half g_h1f[BTOK * KSEL * HDIM];
__device__ __half g_h2f[BTOK * KSEL * HDIM];
__device__ __half g_fusedf[BTOK * HDIM];
__device__ float  g_o1[BTOK * 512];
__device__ __half g_ew1f[NEXP * DIN * HDIM];   // fp16 weights, NATURAL [K,N] layout
__device__ __half g_ew2f[NEXP * HDIM * HDIM];
__device__ __half g_fw1f[HDIM * 512];
__device__ __half g_gw1h[DIN * HDIM];          // gate W1 hi/lo [N,K]
__device__ __half g_gw1l[DIN * HDIM];

__device__ __forceinline__ float gelu_f(float x) {
    return 0.5f * x * (1.0f + erff(x * 0.70710678118654752440f));
}
__device__ __forceinline__ uint32_t smem_u32(const void* p) {
    uint32_t a;
    asm("{ .reg .u64 t; cvta.to.shared.u64 t, %1; cvt.u32.u64 %0, t; }" : "=r"(a) : "l"(p));
    return a;
}
__device__ __forceinline__ uint4 ldm4(uint32_t addr) {
    uint4 r;
    asm volatile("ldmatrix.sync.aligned.m8n8.x4.shared.b16 {%0,%1,%2,%3}, [%4];"
                 : "=r"(r.x), "=r"(r.y), "=r"(r.z), "=r"(r.w) : "r"(addr));
    return r;
}
__device__ __forceinline__ uint4 ldm4t(uint32_t addr) {
    uint4 r;
    asm volatile("ldmatrix.sync.aligned.m8n8.x4.trans.shared.b16 {%0,%1,%2,%3}, [%4];"
                 : "=r"(r.x), "=r"(r.y), "=r"(r.z), "=r"(r.w) : "r"(addr));
    return r;
}
__device__ __forceinline__ void mma_fp16(float* c, const uint4& a, uint32_t b0, uint32_t b1) {
    asm volatile(
        "mma.sync.aligned.m16n8k16.row.col.f32.f16.f16.f32 "
        "{%0,%1,%2,%3}, {%4,%5,%6,%7}, {%8,%9}, {%0,%1,%2,%3};"
        : "+f"(c[0]), "+f"(c[1]), "+f"(c[2]), "+f"(c[3])
        : "r"(a.x), "r"(a.y), "r"(a.z), "r"(a.w), "r"(b0), "r"(b1));
}
__device__ __forceinline__ uint32_t pkh(__half a, __half b) {
    return (uint32_t)__half_as_ushort(a) | ((uint32_t)__half_as_ushort(b) << 16);
}
__device__ __forceinline__ void split2h(float x, __half& h, __half& l) {
    h = __float2half_rn(x);
    l = __float2half_rn(x - __half2float(h));
}

// ---- concat -> fp16 hi/lo planes ----
__global__ void concat_kernel(const float* __restrict__ wifi, const float* __restrict__ rfid,
                              __half* __restrict__ ch, __half* __restrict__ cl) {
    int i = blockIdx.x * 256 + threadIdx.x;
    if (i < BTOK * DIN) {
        int b = i >> 9, c = i & 511;
        float v = (c < 256) ? wifi[b * 256 + c] : rfid[b * 256 + (c - 256)];
        __half h, l; split2h(v, h, l);
        ch[i] = h; cl[i] = l;
    }
}

// ---- weight fp32 -> fp16 convert, SAME layout (no transpose) ----
__global__ void wconv_kernel(const float* __restrict__ W, __half* __restrict__ Tf, int n4) {
    int i = blockIdx.x * 256 + threadIdx.x;
    if (i < n4) {
        float4 v = *(const float4*)(W + (size_t)i * 4);
        uint2 o;
        o.x = pkh(__float2half_rn(v.x), __float2half_rn(v.y));
        o.y = pkh(__float2half_rn(v.z), __float2half_rn(v.w));
        *(uint2*)(Tf + (size_t)i * 4) = o;
    }
}

// ---- gate weight transpose + fp16 hi/lo split (small) ----
__global__ void wsplit2_kernel(const float* __restrict__ W,
                               __half* __restrict__ Th, __half* __restrict__ Tl,
                               int K, int N) {
    __shared__ float tile[32][33];
    int k0 = blockIdx.y * 32, n0 = blockIdx.x * 32;
    int tx = threadIdx.x, ty = threadIdx.y;
#pragma unroll
    for (int i = 0; i < 32; i += 8)
        tile[ty + i][tx] = W[(size_t)(k0 + ty + i) * N + n0 + tx];
    __syncthreads();
#pragma unroll
    for (int i = 0; i < 32; i += 8) {
        int n = n0 + ty + i, k = k0 + tx;
        __half h, l; split2h(tile[tx][ty + i], h, l);
        Th[(size_t)n * K + k] = h;
        Tl[(size_t)n * K + k] = l;
    }
}

// ---------------------------------------------------------------------------
// fp16 1-pass HMMA GEMM, B in NATURAL [K,N] layout via ldmatrix.trans.
// A fp16 [M,K] (80B padded rows); B smem: 32 k-rows x 272B padded.
// Buffer: A@0 (10240) + B@10240 (8704) = 18944; x2 double-buffer. occ 2.
// ---------------------------------------------------------------------------
static constexpr int WG_SMEM = 2 * 18944;

template<bool SEG, bool GATHER, bool SCATTER, bool BN, bool OUTS>
__global__ void __launch_bounds__(256, 2) w_gemm(
    const __half* __restrict__ Ap, const __half* __restrict__ Bp,
    float* __restrict__ C, __half* __restrict__ Cf,
    int Mfixed, int N, int K,
    const int* __restrict__ offsets, const int* __restrict__ rowinfo,
    const float* __restrict__ bias,
    const float* __restrict__ bng, const float* __restrict__ bnb,
    const float* __restrict__ bnm, const float* __restrict__ bnv)
{
    extern __shared__ __align__(16) char sm[];
    int m0 = 0, M = Mfixed;
    if (SEG) {
        int e = blockIdx.z;
        m0 = offsets[e];
        M  = offsets[e + 1] - m0;
        Bp += (size_t)e * K * N;
        bias += (size_t)e * N;
        if (BN) { bng += (size_t)e * N; bnb += (size_t)e * N;
                  bnm += (size_t)e * N; bnv += (size_t)e * N; }
    }
    const int mtile = blockIdx.x * 128;
    if (mtile >= M) return;
    const int ntile = blockIdx.y * 128;

    const int tid = threadIdx.x, lane = tid & 31, wid = tid >> 5;
    const int warpM = wid & 3, warpN = wid >> 2;
    const uint32_t smBase = smem_u32(sm);

    // A fill: 4 rows/thread, 8B per row
    const int acg = tid & 7;
    const __half* aP[4]; bool aval[4]; uint32_t aDst[4];
#pragma unroll
    for (int i = 0; i < 4; i++) {
        int row = (tid >> 3) + i * 32;
        bool v = (mtile + row) < M;
        aval[i] = v;
        int tok = 0;
        if (v) { int gr = m0 + mtile + row; tok = GATHER ? (rowinfo[gr] >> 2) : gr; }
        aP[i] = Ap + (size_t)tok * K + acg * 4;
        aDst[i] = (uint32_t)(row * 80 + acg * 8);
    }
    // B fill from [K,N]: 32 k-rows x 128 n-cols = 512 x 16B, 2/thread
    const __half* bP[2]; uint32_t bDst[2];
#pragma unroll
    for (int i = 0; i < 2; i++) {
        int idx = tid + (i << 8);
        int row = idx >> 4, cg = idx & 15;
        bP[i] = Bp + (size_t)row * N + ntile + cg * 8;
        bDst[i] = 10240u + (uint32_t)(row * 272 + cg * 16);
    }
    const size_t bChunkStep = (size_t)32 * N;

    const int qa = lane >> 3, ra = lane & 7;
    const int lrow = ((qa & 1) << 3) + ra;
    const int lcolB = ((qa >> 1) << 3) * 2;
    const uint32_t aFragOff = (uint32_t)((warpM * 32 + lrow) * 80) + lcolB;
    // B trans fragments: matrix idx = lane>>3 -> nh = idx&1, kh = idx>>1
    const int blk = lane >> 3, lr = lane & 7;
    const int nh = blk & 1, kh = blk >> 1;
    const uint32_t bFragOff = 10240u + (uint32_t)((kh * 8 + lr) * 272)
                            + (uint32_t)(nh * 16) + (uint32_t)(warpN * 128);

    float acc[2][8][4];
#pragma unroll
    for (int mt = 0; mt < 2; mt++)
#pragma unroll
        for (int nt = 0; nt < 8; nt++)
#pragma unroll
            for (int q = 0; q < 4; q++) acc[mt][nt][q] = 0.0f;

    const int NC = K >> 5;
    const uint2 z2 = make_uint2(0u, 0u);

    {
        char* base = sm;
#pragma unroll
        for (int i = 0; i < 4; i++)
            *(uint2*)(base + aDst[i]) = aval[i] ? *(const uint2*)aP[i] : z2;
#pragma unroll
        for (int i = 0; i < 2; i++)
            *(uint4*)(base + bDst[i]) = *(const uint4*)bP[i];
    }
    __syncthreads();

    for (int c = 0; c < NC; c++) {
        uint2 aR[4]; uint4 bR[2];
        const bool pf = (c + 1) < NC;
        if (pf) {
            const int kc = (c + 1) << 5;
#pragma unroll
            for (int i = 0; i < 4; i++)
                aR[i] = aval[i] ? *(const uint2*)(aP[i] + kc) : z2;
            const size_t bo = (size_t)(c + 1) * bChunkStep;
#pragma unroll
            for (int i = 0; i < 2; i++)
                bR[i] = *(const uint4*)(bP[i] + bo);
        }
        const uint32_t bb = smBase + (uint32_t)(c & 1) * 18944u;
#pragma unroll
        for (int ks = 0; ks < 2; ks++) {
            uint4 ah[2];
#pragma unroll
            for (int mt = 0; mt < 2; mt++)
                ah[mt] = ldm4(bb + aFragOff + mt * 1280u + ks * 32u);
            uint32_t bf[8][2];
#pragma unroll
            for (int np = 0; np < 4; np++) {
                uint4 t = ldm4t(bb + bFragOff + (uint32_t)(ks * 16 * 272) + np * 32u);
                // t.x=(kLo,nLo) t.y=(kLo,nHi) t.z=(kHi,nLo) t.w=(kHi,nHi)
                bf[2*np][0]   = t.x; bf[2*np][1]   = t.z;
                bf[2*np+1][0] = t.y; bf[2*np+1][1] = t.w;
            }
#pragma unroll
            for (int mt = 0; mt < 2; mt++)
#pragma unroll
                for (int nt = 0; nt < 8; nt++)
                    mma_fp16(acc[mt][nt], ah[mt], bf[nt][0], bf[nt][1]);
        }
        if (pf) {
            char* base = sm + ((c + 1) & 1) * 18944;
#pragma unroll
            for (int i = 0; i < 4; i++)
                *(uint2*)(base + aDst[i]) = aR[i];
#pragma unroll
            for (int i = 0; i < 2; i++)
                *(uint4*)(base + bDst[i]) = bR[i];
        }
        __syncthreads();
    }

    const int g = lane >> 2, tt = lane & 3;
#pragma unroll
    for (int mt = 0; mt < 2; mt++) {
#pragma unroll
        for (int half = 0; half < 2; half++) {
            int rl = mtile + warpM * 32 + mt * 16 + half * 8 + g;
            if (rl < M) {
                int gr = m0 + rl;
                int crow = SCATTER ? rowinfo[gr] : gr;
                size_t rowoff = (size_t)crow * N;
#pragma unroll
                for (int nt = 0; nt < 8; nt++) {
                    int cn = ntile + warpN * 64 + nt * 8 + tt * 2;
                    float x0 = acc[mt][nt][half * 2 + 0] + __ldg(bias + cn);
                    float x1 = acc[mt][nt][half * 2 + 1] + __ldg(bias + cn + 1);
                    if (BN) {
                        x0 = gelu_f((x0 - __ldg(bnm + cn)) * rsqrtf(__ldg(bnv + cn) + EPSN)
                                    * __ldg(bng + cn) + __ldg(bnb + cn));
                        x1 = gelu_f((x1 - __ldg(bnm + cn + 1)) * rsqrtf(__ldg(bnv + cn + 1) + EPSN)
                                    * __ldg(bng + cn + 1) + __ldg(bnb + cn + 1));
                    }
                    if (OUTS) {
                        *(uint32_t*)(Cf + rowoff + cn) =
                            pkh(__float2half_rn(x0), __float2half_rn(x1));
                    } else {
                        *(float2*)(C + rowoff + cn) = make_float2(x0, x1);
                    }
                }
            }
        }
    }
}

// ---------------------------------------------------------------------------
// Gate GEMM: fp16 3-pass with [N,K] hi/lo planes (unchanged).
// ---------------------------------------------------------------------------
static constexpr int GG_SMEM = 2 * 40960;

__global__ void __launch_bounds__(256, 1) gate_hmma(
    const __half* __restrict__ Ahp, const __half* __restrict__ Alp,
    const __half* __restrict__ Bhp, const __half* __restrict__ Blp,
    float* __restrict__ C, const float* __restrict__ bias)
{
    extern __shared__ __align__(16) char sm[];
    const int N = HDIM, K = DIN;
    const int mtile = blockIdx.x * 128, ntile = blockIdx.y * 128;
    const int tid = threadIdx.x, lane = tid & 31, wid = tid >> 5;
    const int warpM = wid & 3, warpN = wid >> 2;
    const uint32_t smBase = smem_u32(sm);

    const int acg = tid & 7;
    const __half* aPh[4]; const __half* aPl[4]; uint32_t aDst[4];
#pragma unroll
    for (int i = 0; i < 4; i++) {
        int row = (tid >> 3) + i * 32;
        size_t off = (size_t)(mtile + row) * K + acg * 4;
        aPh[i] = Ahp + off; aPl[i] = Alp + off;
        aDst[i] = (uint32_t)(row * 80 + acg * 8);
    }
    const __half* bPtr[4]; uint32_t bDst[4];
#pragma unroll
    for (int i = 0; i < 4; i++) {
        int idx = tid + (i << 8);
        int plane = idx >> 9, f = idx & 511;
        int row = f >> 2, cg = f & 3;
        bPtr[i] = (plane ? Blp : Bhp) + (size_t)(ntile + row) * K + cg * 8;
        bDst[i] = (plane ? 30720u : 20480u) + (uint32_t)(row * 80 + cg * 16);
    }

    const int qa = lane >> 3, ra = lane & 7;
    const int lrow = ((qa & 1) << 3) + ra;
    const int lcolB = ((qa >> 1) << 3) * 2;
    const uint32_t aFragOff = (uint32_t)((warpM * 32 + lrow) * 80) + lcolB;
    const uint32_t bFragOff = (uint32_t)((warpN * 64 + lrow) * 80) + lcolB + 20480u;

    float acc[2][8][4];
#pragma unroll
    for (int mt = 0; mt < 2; mt++)
#pragma unroll
        for (int nt = 0; nt < 8; nt++)
#pragma unroll
            for (int q = 0; q < 4; q++) acc[mt][nt][q] = 0.0f;

    const int NC = K >> 5;
    {
        char* base = sm;
#pragma unroll
        for (int i = 0; i < 4; i++) {
            *(uint2*)(base + aDst[i])         = *(const uint2*)aPh[i];
            *(uint2*)(base + 10240 + aDst[i]) = *(const uint2*)aPl[i];
        }
#pragma unroll
        for (int i = 0; i < 4; i++)
            *(uint4*)(base + bDst[i]) = *(const uint4*)bPtr[i];
    }
    __syncthreads();

    for (int c = 0; c < NC; c++) {
        uint2 aRh[4], aRl[4]; uint4 bR[4];
        const bool pf = (c + 1) < NC;
        if (pf) {
            const int kc = (c + 1) << 5;
#pragma unroll
            for (int i = 0; i < 4; i++) {
                aRh[i] = *(const uint2*)(aPh[i] + kc);
                aRl[i] = *(const uint2*)(aPl[i] + kc);
            }
#pragma unroll
            for (int i = 0; i < 4; i++)
                bR[i] = *(const uint4*)(bPtr[i] + kc);
        }
        const uint32_t bb = smBase + (uint32_t)(c & 1) * 40960u;
#pragma unroll
        for (int ks = 0; ks < 2; ks++) {
            const uint32_t kso = ks * 32;
            uint4 ah[2], al[2];
#pragma unroll
            for (int mt = 0; mt < 2; mt++) {
                uint32_t ao = bb + aFragOff + mt * 1280u + kso;
                ah[mt] = ldm4(ao);
                al[mt] = ldm4(ao + 10240u);
            }
            uint32_t bh[8][2], bl[8][2];
#pragma unroll
            for (int np = 0; np < 4; np++) {
                uint32_t bo = bb + bFragOff + np * 1280u + kso;
                uint4 h = ldm4(bo);
                uint4 l = ldm4(bo + 10240u);
                bh[2*np][0] = h.x; bh[2*np][1] = h.z;
                bh[2*np+1][0] = h.y; bh[2*np+1][1] = h.w;
                bl[2*np][0] = l.x; bl[2*np][1] = l.z;
                bl[2*np+1][0] = l.y; bl[2*np+1][1] = l.w;
            }
#pragma unroll
            for (int mt = 0; mt < 2; mt++)
#pragma unroll
                for (int nt = 0; nt < 8; nt++) {
                    mma_fp16(acc[mt][nt], ah[mt], bh[nt][0], bh[nt][1]);
                    mma_fp16(acc[mt][nt], al[mt], bh[nt][0], bh[nt][1]);
                    mma_fp16(acc[mt][nt], ah[mt], bl[nt][0], bl[nt][1]);
                }
        }
        if (pf) {
            char* base = sm + ((c + 1) & 1) * 40960;
#pragma unroll
            for (int i = 0; i < 4; i++) {
                *(uint2*)(base + aDst[i])         = aRh[i];
                *(uint2*)(base + 10240 + aDst[i]) = aRl[i];
            }
#pragma unroll
            for (int i = 0; i < 4; i++)
                *(uint4*)(base + bDst[i]) = bR[i];
        }
        __syncthreads();
    }

    const int g = lane >> 2, tt = lane & 3;
#pragma unroll
    for (int mt = 0; mt < 2; mt++) {
#pragma unroll
        for (int half = 0; half < 2; half++) {
            int rl = mtile + warpM * 32 + mt * 16 + half * 8 + g;
            float* cp = C + (size_t)rl * N;
#pragma unroll
            for (int nt = 0; nt < 8; nt++) {
                int cn = ntile + warpN * 64 + nt * 8 + tt * 2;
                float x0 = acc[mt][nt][half * 2 + 0] + __ldg(bias + cn);
                float x1 = acc[mt][nt][half * 2 + 1] + __ldg(bias + cn + 1);
                *(float2*)(cp + cn) = make_float2(x0, x1);
            }
        }
    }
}

// ---- LayerNorm + GELU (in place) ----
__global__ void ln_gelu_kernel(float* __restrict__ x, const float* __restrict__ g,
                               const float* __restrict__ b) {
    int row = blockIdx.x;
    float* xr = x + (size_t)row * HDIM;
    int t = threadIdx.x;
    float4 v = *(float4*)&xr[t * 4];
    float s = v.x + v.y + v.z + v.w;
    float q = v.x * v.x + v.y * v.y + v.z * v.z + v.w * v.w;
#pragma unroll
    for (int o = 16; o; o >>= 1) {
        s += __shfl_down_sync(0xffffffffu, s, o);
        q += __shfl_down_sync(0xffffffffu, q, o);
    }
    __shared__ float ss[8], qq[8];
    int w = t >> 5, l = t & 31;
    if (l == 0) { ss[w] = s; qq[w] = q; }
    __syncthreads();
    if (w == 0) {
        s = (l < 8) ? ss[l] : 0.0f;
        q = (l < 8) ? qq[l] : 0.0f;
#pragma unroll
        for (int o = 4; o; o >>= 1) {
            s += __shfl_down_sync(0xffffffffu, s, o);
            q += __shfl_down_sync(0xffffffffu, q, o);
        }
        if (l == 0) { ss[0] = s; qq[0] = q; }
    }
    __syncthreads();
    float mu  = ss[0] * (1.0f / HDIM);
    float var = qq[0] * (1.0f / HDIM) - mu * mu;
    float r = rsqrtf(var + EPSN);
    float4 gv = *(const float4*)&g[t * 4];
    float4 bv = *(const float4*)&b[t * 4];
    v.x = gelu_f((v.x - mu) * r * gv.x + bv.x);
    v.y = gelu_f((v.y - mu) * r * gv.y + bv.y);
    v.z = gelu_f((v.z - mu) * r * gv.z + bv.z);
    v.w = gelu_f((v.w - mu) * r * gv.w + bv.w);
    *(float4*)&xr[t * 4] = v;
}

// ---- gate logits + softmax + top4 + renorm ----
__global__ void gate_topk_kernel(const float* __restrict__ g1, const float* __restrict__ w2,
                                 const float* __restrict__ b2, int* __restrict__ tidx,
                                 float* __restrict__ tw, int* __restrict__ counts) {
    int b = blockIdx.x, t = threadIdx.x;
    int e = t >> 3, sub = t & 7;
    const float* row = g1 + (size_t)b * HDIM;
    float s = 0.0f;
    for (int k = sub; k < HDIM; k += 8) s += row[k] * w2[k * NEXP + e];
    s += __shfl_down_sync(0xffffffffu, s, 4);
    s += __shfl_down_sync(0xffffffffu, s, 2);
    s += __shfl_down_sync(0xffffffffu, s, 1);
    __shared__ float logit[NEXP];
    if (sub == 0) logit[e] = s + b2[e];
    __syncthreads();
    if (t == 0) {
        float mx = -1e30f;
        for (int i = 0; i < NEXP; i++) mx = fmaxf(mx, logit[i]);
        float p[NEXP], sum = 0.0f;
        for (int i = 0; i < NEXP; i++) { p[i] = expf(logit[i] - mx); sum += p[i]; }
        float inv = 1.0f / sum;
        bool used[NEXP];
        for (int i = 0; i < NEXP; i++) used[i] = false;
        int idx[KSEL]; float val[KSEL];
        for (int tk = 0; tk < KSEL; tk++) {
            int best = -1; float bv = -1e30f;
            for (int i = 0; i < NEXP; i++)
                if (!used[i] && p[i] > bv) { bv = p[i]; best = i; }
            used[best] = true; idx[tk] = best; val[tk] = bv * inv;
        }
        float m2 = val[0], e2[KSEL], s2 = 0.0f;
        for (int tk = 0; tk < KSEL; tk++) { e2[tk] = expf(val[tk] - m2); s2 += e2[tk]; }
        float inv2 = 1.0f / s2;
        for (int tk = 0; tk < KSEL; tk++) {
            tidx[b * KSEL + tk] = idx[tk];
            tw[b * KSEL + tk]   = e2[tk] * inv2;
            atomicAdd(&counts[idx[tk]], 1);
        }
    }
}

// ---- dispatch bookkeeping ----
__global__ void reset_kernel(int* __restrict__ counts) {
    if (threadIdx.x < NEXP) counts[threadIdx.x] = 0;
}
__global__ void scan_kernel(const int* __restrict__ counts, int* __restrict__ offsets,
                            int* __restrict__ cursor) {
    if (threadIdx.x == 0) {
        int acc = 0;
        for (int e = 0; e < NEXP; e++) { offsets[e] = acc; cursor[e] = acc; acc += counts[e]; }
        offsets[NEXP] = acc;
    }
}
__global__ void scatter_kernel(const int* __restrict__ tidx, int* __restrict__ cursor,
                               int* __restrict__ rowinfo) {
    int i = blockIdx.x * 256 + threadIdx.x;
    if (i < BTOK * KSEL) {
        int pos = atomicAdd(&cursor[tidx[i]], 1);
        rowinfo[pos] = i;
    }
}

// ---- weighted top-k combine (fp16 in/out) ----
__global__ void combine_kernel(const __half* __restrict__ h2f, const float* __restrict__ tw,
                               __half* __restrict__ ff) {
    int idx = blockIdx.x * 256 + threadIdx.x;
    if (idx < BTOK * HDIM) {
        int b = idx >> 10, h = idx & (HDIM - 1);
        const __half* base = h2f + ((size_t)b * KSEL) * HDIM + h;
        const float* w = tw + b * KSEL;
        float v = w[0] * __half2float(base[0]) + w[1] * __half2float(base[HDIM])
                + w[2] * __half2float(base[2 * HDIM]) + w[3] * __half2float(base[3 * HDIM]);
        ff[idx] = __float2half_rn(v);
    }
}

// ---- final head GEMM [4096,512]x[512,20] ----
__global__ void final_kernel(const float* __restrict__ o1, const float* __restrict__ w2,
                             const float* __restrict__ b2, float* __restrict__ out) {
    int b = blockIdx.x;
    __shared__ float row[512];
    int t = threadIdx.x;
    for (int k = t; k < 512; k += 160) row[k] = o1[(size_t)b * 512 + k];
    __syncthreads();
    int c = t >> 3, sub = t & 7;
    float s = 0.0f;
    for (int k = sub; k < 512; k += 8) s += row[k] * w2[k * NCLS + c];
    s += __shfl_down_sync(0xffffffffu, s, 4);
    s += __shfl_down_sync(0xffffffffu, s, 2);
    s += __shfl_down_sync(0xffffffffu, s, 1);
    if (sub == 0) out[b * NCLS + c] = s + b2[c];
}

// ---- launch ----
extern "C" void kernel_launch(void* const* d_in, const int* in_sizes, int n_in,
                              void* d_out, int out_size) {
    const float* wifi      = (const float*)d_in[0];
    const float* rfid      = (const float*)d_in[1];
    const float* gate_w1   = (const float*)d_in[2];
    const float* gate_b1   = (const float*)d_in[3];
    const float* gate_ln_g = (const float*)d_in[4];
    const float* gate_ln_b = (const float*)d_in[5];
    const float* gate_w2   = (const float*)d_in[6];
    const float* gate_b2   = (const float*)d_in[7];
    const float* exp_w1    = (const float*)d_in[8];
    const float* exp_b1    = (const float*)d_in[9];
    const float* exp_bn1_g = (const float*)d_in[10];
    const float* exp_bn1_b = (const float*)d_in[11];
    const float* exp_bn1_m = (const float*)d_in[12];
    const float* exp_bn1_v = (const float*)d_in[13];
    const float* exp_w2    = (const float*)d_in[14];
    const float* exp_b2    = (const float*)d_in[15];
    const float* exp_bn2_g = (const float*)d_in[16];
    const float* exp_bn2_b = (const float*)d_in[17];
    const float* exp_bn2_m = (const float*)d_in[18];
    const float* exp_bn2_v = (const float*)d_in[19];
    const float* fin_w1    = (const float*)d_in[20];
    const float* fin_b1    = (const float*)d_in[21];
    const float* fin_bn_g  = (const float*)d_in[22];
    const float* fin_bn_b  = (const float*)d_in[23];
    const float* fin_bn_m  = (const float*)d_in[24];
    const float* fin_bn_v  = (const float*)d_in[25];
    const float* fin_w2    = (const float*)d_in[26];
    const float* fin_b2    = (const float*)d_in[27];
    float* out = (float*)d_out;

    float *g1, *tw, *o1;
    int *tidx, *counts, *cursor, *offsets, *rowinfo;
    __half *combh, *combl, *h1f, *h2f, *fusedf, *ew1f, *ew2f, *fw1f, *gw1h, *gw1l;
    cudaGetSymbolAddress((void**)&combh,    g_combh);
    cudaGetSymbolAddress((void**)&combl,    g_combl);
    cudaGetSymbolAddress((void**)&g1,       g_g1);
    cudaGetSymbolAddress((void**)&tidx,     g_tidx);
    cudaGetSymbolAddress((void**)&tw,       g_tw);
    cudaGetSymbolAddress((void**)&counts,   g_counts);
    cudaGetSymbolAddress((void**)&cursor,   g_cursor);
    cudaGetSymbolAddress((void**)&offsets,  g_offsets);
    cudaGetSymbolAddress((void**)&rowinfo,  g_rowinfo);
    cudaGetSymbolAddress((void**)&h1f,      g_h1f);
    cudaGetSymbolAddress((void**)&h2f,      g_h2f);
    cudaGetSymbolAddress((void**)&fusedf,   g_fusedf);
    cudaGetSymbolAddress((void**)&o1,       g_o1);
    cudaGetSymbolAddress((void**)&ew1f,     g_ew1f);
    cudaGetSymbolAddress((void**)&ew2f,     g_ew2f);
    cudaGetSymbolAddress((void**)&fw1f,     g_fw1f);
    cudaGetSymbolAddress((void**)&gw1h,     g_gw1h);
    cudaGetSymbolAddress((void**)&gw1l,     g_gw1l);

    cudaFuncSetAttribute(w_gemm<true, true, false, true, true>,
                         cudaFuncAttributeMaxDynamicSharedMemorySize, WG_SMEM);
    cudaFuncSetAttribute(w_gemm<true, false, true, true, true>,
                         cudaFuncAttributeMaxDynamicSharedMemorySize, WG_SMEM);
    cudaFuncSetAttribute(w_gemm<false, false, false, true, false>,
                         cudaFuncAttributeMaxDynamicSharedMemorySize, WG_SMEM);
    cudaFuncSetAttribute(gate_hmma,
                         cudaFuncAttributeMaxDynamicSharedMemorySize, GG_SMEM);

    // weight fp16 conversion (no transpose; natural [K,N] layout)
    wconv_kernel<<<(NEXP * DIN * HDIM / 4 + 255) / 256, 256>>>(exp_w1, ew1f, NEXP * DIN * HDIM / 4);
    wconv_kernel<<<(NEXP * HDIM * HDIM / 4 + 255) / 256, 256>>>(exp_w2, ew2f, NEXP * HDIM * HDIM / 4);
    wconv_kernel<<<(HDIM * 512 / 4 + 255) / 256, 256>>>(fin_w1, fw1f, HDIM * 512 / 4);
    wsplit2_kernel<<<dim3(32, 16), dim3(32, 8)>>>(gate_w1, gw1h, gw1l, DIN, HDIM);

    // 1. concat
    concat_kernel<<<(BTOK * DIN + 255) / 256, 256>>>(wifi, rfid, combh, combl);
    // 2. gate GEMM1 (fp16 3-pass, near-fp32)
    gate_hmma<<<dim3(32, 8), 256, GG_SMEM>>>(combh, combl, gw1h, gw1l, g1, gate_b1);
    // 3. LN + GELU
    ln_gelu_kernel<<<BTOK, 256>>>(g1, gate_ln_g, gate_ln_b);
    // 4. gate top-4
    reset_kernel<<<1, 32>>>(counts);
    gate_topk_kernel<<<BTOK, 128>>>(g1, gate_w2, gate_b2, tidx, tw, counts);
    // 5. dispatch
    scan_kernel<<<1, 1>>>(counts, offsets, cursor);
    scatter_kernel<<<(BTOK * KSEL + 255) / 256, 256>>>(tidx, cursor, rowinfo);
    // 6. expert GEMM1 (gather, BN1+GELU, fp16 output)
    w_gemm<true, true, false, true, true><<<dim3(32, 8, NEXP), 256, WG_SMEM>>>(
        combh, ew1f, nullptr, h1f, 0, HDIM, DIN,
        offsets, rowinfo, exp_b1, exp_bn1_g, exp_bn1_b, exp_bn1_m, exp_bn1_v);
    // 7. expert GEMM2 (scatter, BN2+GELU, fp16 output)
    w_gemm<true, false, true, true, true><<<dim3(32, 8, NEXP), 256, WG_SMEM>>>(
        h1f, ew2f, nullptr, h2f, 0, HDIM, HDIM,
        offsets, rowinfo, exp_b2, exp_bn2_g, exp_bn2_b, exp_bn2_m, exp_bn2_v);
    // 8. combine -> fp16 plane
    combine_kernel<<<(BTOK * HDIM + 255) / 256, 256>>>(h2f, tw, fusedf);
    // 9. final GEMM1 (BN+GELU, fp32 output)
    w_gemm<false, false, false, true, false><<<dim3(32, 4, 1), 256, WG_SMEM>>>(
        fusedf, fw1f, o1, nullptr, BTOK, 512, HDIM,
        nullptr, nullptr, fin_b1, fin_bn_g, fin_bn_b, fin_bn_m, fin_bn_v);
    // 10. head
    final_kernel<<<BTOK, 160>>>(o1, fin_w2, fin_b2, out);
}